// round 7
// baseline (speedup 1.0000x reference)
#include <cuda_runtime.h>
#include <math.h>
#include <stdint.h>

#define BATCH 8192
#define PDIM  512
#define DM    256
#define DI    512
#define DTR   16
#define DS    16
#define ADIM  64
#define XDW   48

// ---- static scratch ----
__device__ float g_X[BATCH * DM];
__device__ float g_U2[BATCH * DI];
__device__ float g_G[BATCH * DI];        // silu(z)
__device__ float g_XD[2 * BATCH * XDW];  // split-K halves
__device__ float g_Y[BATCH * DI];
__device__ float g_H[BATCH * DM];

__device__ __forceinline__ float cvt_tf32(float x) {
    uint32_t u;
    asm("cvt.rna.tf32.f32 %0, %1;" : "=r"(u) : "f"(x));
    return __uint_as_float(u);
}

__device__ __forceinline__ void mma_tf32(float* c, const uint32_t* a,
                                         uint32_t b0, uint32_t b1) {
    asm volatile(
        "mma.sync.aligned.m16n8k8.row.col.f32.tf32.tf32.f32 "
        "{%0,%1,%2,%3},{%4,%5,%6,%7},{%8,%9},{%0,%1,%2,%3};"
        : "+f"(c[0]), "+f"(c[1]), "+f"(c[2]), "+f"(c[3])
        : "r"(a[0]), "r"(a[1]), "r"(a[2]), "r"(a[3]), "r"(b0), "r"(b1));
}

// ---- fast transcendentals ----
__device__ __forceinline__ float fast_sigmoid(float x) {
    return __fdividef(1.f, 1.f + __expf(-x));
}
__device__ __forceinline__ float fast_softplus(float x) {
    return (x > 15.f) ? x : __logf(1.f + __expf(x));
}
__device__ __forceinline__ float fast_tanh(float x) {
    float e = __expf(-2.f * fabsf(x));
    float t = __fdividef(1.f - e, 1.f + e);
    return copysignf(t, x);
}

// Paired layout: row's 16 k-cols stored as float2 pairs (c, c+4):
//   float position of col c: ks=c>>3, t=c&3 (c&4 selects pair half)
//   pos = (ks*4 + (c&3))*2 + ((c>>2)&1)
// A float4 gmem load of cols ak..ak+3 writes positions base, base+2, base+4,
// base+6 with base = (ak & 8) | ((ak >> 2) & 1).
// Fragment read: float2 at [row][(ks*4+t)*2] = (col kb+t, col kb+t+4).

// C[M,N] = A[M,K] @ W[N,K]^T, tf32 MMA. BM=128 BN=64 BK=16, 256 thr,
// warp tile 32x32, LDS.64 paired fragments, double-buffered.
// EPI: 0 plain(guard), 1 +bias, 2 in_proj fused (U2|G), 3 dual heads
template <int EPI>
__global__ void __launch_bounds__(256)
gemm_tc(const float* __restrict__ A, int lda,
        const float* __restrict__ W, int ldw, const float* __restrict__ bias,
        float* __restrict__ C, int ldc, int M, int N, int K,
        const float* __restrict__ aux0, const float* __restrict__ aux1,
        float* __restrict__ aux2) {
    const int BM = 128, BN = 64, BK = 16, PAD = 24;
    __shared__ float As[2][BM][PAD];
    __shared__ float Ws[2][BN][PAD];

    const int tid  = threadIdx.x;
    const int lane = tid & 31, wid = tid >> 5;
    const int wm = (wid & 3) * 32, wn = (wid >> 2) * 32;
    const int g = lane >> 2, t = lane & 3;
    const int bm = blockIdx.x * BM;
    const int bn = (EPI == 3) ? 0 : blockIdx.y * BN;

    // split-K via blockIdx.z (used by x_proj stage): offset A cols / W cols,
    // separate C buffer per z half.
    const int kz = blockIdx.z * K;
    const float* Az = A + kz;
    const float* Wz0 = W + kz;

    const float* Wp = Wz0;
    const float* bp = bias;
    float* Cp = C + (size_t)blockIdx.z * BATCH * XDW;  // only stage3 has z>0
    if (EPI != 3) { /* Cp as set */ } 
    if (EPI == 3) {
        Cp = C;
        if (blockIdx.y == 1) { Wp = aux0; bp = aux1; Cp = aux2; }
    }

    const int ar0 = tid >> 2;
    const int ak  = (tid & 3) * 4;
    const int sbase = (ak & 8) | ((ak >> 2) & 1);
    const int nTiles = K / BK;

    float acc[2][4][4];
#pragma unroll
    for (int i = 0; i < 2; i++)
#pragma unroll
        for (int j = 0; j < 4; j++)
#pragma unroll
            for (int l = 0; l < 4; l++) acc[i][j][l] = 0.f;

    auto stA = [&](int buf, int row, float4 v) {
        As[buf][row][sbase + 0] = cvt_tf32(v.x);
        As[buf][row][sbase + 2] = cvt_tf32(v.y);
        As[buf][row][sbase + 4] = cvt_tf32(v.z);
        As[buf][row][sbase + 6] = cvt_tf32(v.w);
    };
    auto stW = [&](int buf, int row, float4 v) {
        Ws[buf][row][sbase + 0] = cvt_tf32(v.x);
        Ws[buf][row][sbase + 2] = cvt_tf32(v.y);
        Ws[buf][row][sbase + 4] = cvt_tf32(v.z);
        Ws[buf][row][sbase + 6] = cvt_tf32(v.w);
    };
    auto ldWg = [&](int n, int k0) -> float4 {
        if (n < N) return *(const float4*)(Wp + (size_t)n * ldw + k0);
        return make_float4(0.f, 0.f, 0.f, 0.f);
    };

    {
        stA(0, ar0,      *(const float4*)(Az + (size_t)(bm + ar0) * lda + ak));
        stA(0, ar0 + 64, *(const float4*)(Az + (size_t)(bm + ar0 + 64) * lda + ak));
        stW(0, ar0, ldWg(bn + ar0, ak));
    }
    __syncthreads();

    for (int kt = 0; kt < nTiles; kt++) {
        const int cur = kt & 1;
        float4 pa0, pa1, pw0;
        const bool more = (kt + 1 < nTiles);
        if (more) {
            int k0 = (kt + 1) * BK;
            pa0 = *(const float4*)(Az + (size_t)(bm + ar0) * lda + k0 + ak);
            pa1 = *(const float4*)(Az + (size_t)(bm + ar0 + 64) * lda + k0 + ak);
            pw0 = ldWg(bn + ar0, k0 + ak);
        }

#pragma unroll
        for (int ks = 0; ks < 2; ks++) {
            const int pp = (ks * 4 + t) * 2;
            uint32_t a[2][4];
#pragma unroll
            for (int mt = 0; mt < 2; mt++) {
                int row = wm + mt * 16 + g;
                float2 v0 = *(const float2*)&As[cur][row][pp];
                float2 v1 = *(const float2*)&As[cur][row + 8][pp];
                a[mt][0] = __float_as_uint(v0.x);
                a[mt][1] = __float_as_uint(v1.x);
                a[mt][2] = __float_as_uint(v0.y);
                a[mt][3] = __float_as_uint(v1.y);
            }
#pragma unroll
            for (int nt = 0; nt < 4; nt++) {
                int nc = wn + nt * 8 + g;
                float2 vb = *(const float2*)&Ws[cur][nc][pp];
                uint32_t b0 = __float_as_uint(vb.x);
                uint32_t b1 = __float_as_uint(vb.y);
                mma_tf32(acc[0][nt], a[0], b0, b1);
                mma_tf32(acc[1][nt], a[1], b0, b1);
            }
        }

        if (more) {
            const int nxt = cur ^ 1;
            stA(nxt, ar0, pa0);
            stA(nxt, ar0 + 64, pa1);
            stW(nxt, ar0, pw0);
        }
        __syncthreads();
    }

#pragma unroll
    for (int mt = 0; mt < 2; mt++) {
#pragma unroll
        for (int nt = 0; nt < 4; nt++) {
#pragma unroll
            for (int ci = 0; ci < 4; ci++) {
                int row = bm + wm + mt * 16 + g + ((ci >= 2) ? 8 : 0);
                int col = bn + wn + nt * 8 + t * 2 + (ci & 1);
                float v = acc[mt][nt][ci];
                if (EPI == 0) {
                    if (col < N) Cp[(size_t)row * ldc + col] = v;
                } else if (EPI == 1) {
                    C[(size_t)row * ldc + col] = v + bias[col];
                } else if (EPI == 2) {
                    if (col < DI) {
                        float u = v * aux0[col * 4 + 3] + aux1[col];
                        C[(size_t)row * DI + col] = u * fast_sigmoid(u);           // U2
                    } else {
                        aux2[(size_t)row * DI + (col - DI)] = v * fast_sigmoid(v); // G
                    }
                } else { // EPI == 3
                    float h = v + bp[col];
                    if (blockIdx.y == 0) h = fast_tanh(h);
                    else                 h = fminf(fmaxf(h, -5.f), 2.f);
                    Cp[(size_t)row * ADIM + col] = h;
                }
            }
        }
    }
}

// Fused: XD = XD0 + XD1 (split-K sum); delta = softplus(XD[:,:16]@dtw^T + b);
// bc = B.C;  Y = U2 * (delta*bc + Dskip) * silu(z).  Pipelined U2/G loads.
#define RB2 16
__global__ void __launch_bounds__(512)
delta_ygate(const float* __restrict__ XD, const float* __restrict__ dtw,
            const float* __restrict__ dtb, const float* __restrict__ U2,
            const float* __restrict__ G, const float* __restrict__ Dskip,
            float* __restrict__ Y) {
    __shared__ float sXD[RB2][XDW];
    __shared__ float sbc[RB2];
    const int tid = threadIdx.x;
    const int r0 = blockIdx.x * RB2;

    if (tid < RB2 * 12) {
        int r = tid / 12, c4 = (tid % 12) * 4;
        float4 x0 = *(const float4*)&XD[(size_t)(r0 + r) * XDW + c4];
        float4 x1 = *(const float4*)&XD[(size_t)BATCH * XDW + (size_t)(r0 + r) * XDW + c4];
        x0.x += x1.x; x0.y += x1.y; x0.z += x1.z; x0.w += x1.w;
        *(float4*)&sXD[r][c4] = x0;
    }
    __syncthreads();
    if (tid < RB2) {
        float s = 0.f;
#pragma unroll
        for (int k = 0; k < DS; k++) s += sXD[tid][DTR + k] * sXD[tid][DTR + DS + k];
        sbc[tid] = s;
    }

    float w[DTR];
#pragma unroll
    for (int i = 0; i < 4; i++)
        *(float4*)&w[i * 4] = *(const float4*)(dtw + (size_t)tid * DTR + i * 4);
    const float bv = dtb[tid];
    const float dv = Dskip[tid];
    __syncthreads();

    size_t base = (size_t)r0 * DI;
    float u = U2[base + tid];
    float gg = G[base + tid];
#pragma unroll
    for (int r = 0; r < RB2; r++) {
        float un, gn;
        if (r + 1 < RB2) {
            size_t bn_ = base + DI;
            un = U2[bn_ + tid];
            gn = G[bn_ + tid];
        }
        float acc = bv;
#pragma unroll
        for (int k = 0; k < DTR; k++) acc += w[k] * sXD[r][k];
        float de = fast_softplus(acc);
        Y[base + tid] = u * (de * sbc[r] + dv) * gg;
        base += DI;
        u = un; gg = gn;
    }
}

extern "C" void kernel_launch(void* const* d_in, const int* in_sizes, int n_in,
                              void* d_out, int out_size) {
    const float* perception = (const float*)d_in[0];
    const float* W_in       = (const float*)d_in[1];
    const float* b_in       = (const float*)d_in[2];
    const float* mu_w       = (const float*)d_in[3];
    const float* mu_b       = (const float*)d_in[4];
    const float* ls_w       = (const float*)d_in[5];
    const float* ls_b       = (const float*)d_in[6];
    const float* in_proj_w  = (const float*)d_in[7];
    const float* conv_w     = (const float*)d_in[8];
    const float* conv_b     = (const float*)d_in[9];
    const float* x_proj_w   = (const float*)d_in[10];
    const float* dt_proj_w  = (const float*)d_in[11];
    const float* dt_proj_b  = (const float*)d_in[12];
    const float* Dskip      = (const float*)d_in[14];
    const float* out_proj_w = (const float*)d_in[15];

    float* out = (float*)d_out;

    float *X, *U2, *G, *XD, *Y, *H;
    cudaGetSymbolAddress((void**)&X, g_X);
    cudaGetSymbolAddress((void**)&U2, g_U2);
    cudaGetSymbolAddress((void**)&G, g_G);
    cudaGetSymbolAddress((void**)&XD, g_XD);
    cudaGetSymbolAddress((void**)&Y, g_Y);
    cudaGetSymbolAddress((void**)&H, g_H);

    const int MB = BATCH / 128;   // 64

    // 1) X = perc @ W_in^T + b_in            [8192,256] K=512
    gemm_tc<1><<<dim3(MB, DM / 64), 256>>>(perception, PDIM, W_in, PDIM, b_in,
                                           X, DM, BATCH, DM, PDIM,
                                           nullptr, nullptr, nullptr);
    // 2) in_proj + silu-conv + silu(z)       [8192,1024] K=256 -> U2, G
    gemm_tc<2><<<dim3(MB, (2 * DI) / 64), 256>>>(X, DM, in_proj_w, DM, nullptr,
                                                 U2, DI, BATCH, 2 * DI, DM,
                                                 conv_w, conv_b, G);
    // 3) XD halves = U2 @ x_proj^T (split-K) [8192,48] K=2x256
    gemm_tc<0><<<dim3(MB, 1, 2), 256>>>(U2, DI, x_proj_w, DI, nullptr,
                                        XD, XDW, BATCH, XDW, 256,
                                        nullptr, nullptr, nullptr);
    // 4) delta + bc + gate -> Y              [8192,512]
    delta_ygate<<<BATCH / RB2, 512>>>(XD, dt_proj_w, dt_proj_b, U2, G, Dskip, Y);
    // 5) H = Y @ out_proj^T                  [8192,256] K=512
    gemm_tc<0><<<dim3(MB, DM / 64), 256>>>(Y, DI, out_proj_w, DI, nullptr,
                                           H, DM, BATCH, DM, DI,
                                           nullptr, nullptr, nullptr);
    // 6) heads: mu (by=0) | log_std (by=1)   [8192,64] K=256
    gemm_tc<3><<<dim3(MB, 2), 256>>>(H, DM, mu_w, DM, mu_b, out, ADIM,
                                     BATCH, ADIM, DM, ls_w, ls_b,
                                     out + (size_t)BATCH * ADIM);
    (void)in_sizes; (void)n_in; (void)out_size;
}

// round 9
// speedup vs baseline: 1.0820x; 1.0820x over previous
#include <cuda_runtime.h>
#include <math.h>
#include <stdint.h>

#define BATCH 8192
#define PDIM  512
#define DM    256
#define DI    512
#define DTR   16
#define DS    16
#define ADIM  64
#define XDW   48

// ---- static scratch ----
__device__ float g_P[BATCH * PDIM];      // tf32-rounded perception
__device__ float g_W[581632];            // tf32-rounded weights (concat)
__device__ float g_X[BATCH * DM];
__device__ float g_U2[BATCH * DI];
__device__ float g_G[BATCH * DI];
__device__ float g_XD[BATCH * XDW];
__device__ float g_Y[BATCH * DI];
__device__ float g_H[BATCH * DM];

// weight offsets inside g_W (floats)
#define OFF_WIN   0          // 256x512
#define OFF_INPJ  131072     // 1024x256
#define OFF_XPJ   393216     // 48x512
#define OFF_OPJ   417792     // 256x512
#define OFF_MUW   548864     // 64x256
#define OFF_LSW   565248     // 64x256
#define NW_TOTAL  581632
#define NP_TOTAL  (BATCH * PDIM)

__device__ __forceinline__ float cvt_tf32(float x) {
    uint32_t u;
    asm("cvt.rna.tf32.f32 %0, %1;" : "=r"(u) : "f"(x));
    return __uint_as_float(u);
}

__device__ __forceinline__ void mma_tf32(float* c, const uint32_t* a,
                                         uint32_t b0, uint32_t b1) {
    asm volatile(
        "mma.sync.aligned.m16n8k8.row.col.f32.tf32.tf32.f32 "
        "{%0,%1,%2,%3},{%4,%5,%6,%7},{%8,%9},{%0,%1,%2,%3};"
        : "+f"(c[0]), "+f"(c[1]), "+f"(c[2]), "+f"(c[3])
        : "r"(a[0]), "r"(a[1]), "r"(a[2]), "r"(a[3]), "r"(b0), "r"(b1));
}

// ---- cp.async ----
__device__ __forceinline__ void cp16(uint32_t dst, const float* src, bool ok) {
    int sz = ok ? 16 : 0;
    asm volatile("cp.async.ca.shared.global [%0], [%1], 16, %2;"
                 :: "r"(dst), "l"(src), "r"(sz) : "memory");
}
#define CP_COMMIT() asm volatile("cp.async.commit_group;" ::: "memory")
#define CP_WAIT1()  asm volatile("cp.async.wait_group 1;" ::: "memory")

// ---- fast transcendentals ----
__device__ __forceinline__ float fast_sigmoid(float x) {
    return __fdividef(1.f, 1.f + __expf(-x));
}
__device__ __forceinline__ float fast_softplus(float x) {
    return (x > 15.f) ? x : __logf(1.f + __expf(x));
}
__device__ __forceinline__ float fast_tanh(float x) {
    float e = __expf(-2.f * fabsf(x));
    float t = __fdividef(1.f - e, 1.f + e);
    return copysignf(t, x);
}

// Pre-round perception + all GEMM weights to tf32 (same operand values the
// old cvt-on-load produced, so rel_err is unchanged).
__global__ void __launch_bounds__(256)
preround(const float* __restrict__ P,
         const float* __restrict__ w_in,  const float* __restrict__ in_proj,
         const float* __restrict__ x_proj, const float* __restrict__ out_proj,
         const float* __restrict__ mu_w,  const float* __restrict__ ls_w,
         float* __restrict__ gP, float* __restrict__ gW) {
    int idx = blockIdx.x * 256 + threadIdx.x;
    if (idx < NP_TOTAL) {
        gP[idx] = cvt_tf32(P[idx]);
        return;
    }
    int j = idx - NP_TOTAL;
    if (j >= NW_TOTAL) return;
    float v;
    if      (j < OFF_INPJ) v = w_in[j - OFF_WIN];
    else if (j < OFF_XPJ)  v = in_proj[j - OFF_INPJ];
    else if (j < OFF_OPJ)  v = x_proj[j - OFF_XPJ];
    else if (j < OFF_MUW)  v = out_proj[j - OFF_OPJ];
    else if (j < OFF_LSW)  v = mu_w[j - OFF_MUW];
    else                   v = ls_w[j - OFF_LSW];
    gW[j] = cvt_tf32(v);
}

// C[M,N] = A[M,K] @ W[N,K]^T. Inputs pre-rounded tf32. BM=128 BN=64 BK=16,
// 256 thr, warp tile 32x32, cp.async 3-stage pipeline, smem [row][20].
// EPI: 0 plain full, 1 X=cvt(v+bias), 2 in_proj fused (U2 cvt | G full),
//      3 dual heads, 4 plain cvt store
template <int EPI>
__global__ void __launch_bounds__(256)
gemm_cp(const float* __restrict__ A, int lda,
        const float* __restrict__ W, int ldw, const float* __restrict__ bias,
        float* __restrict__ C, int ldc, int Nfull, int K,
        const float* __restrict__ aux0, const float* __restrict__ aux1,
        float* __restrict__ aux2) {
    const int BM = 128, BN = 64, BK = 16, PAD = 20;
    __shared__ float As[3][BM][PAD];
    __shared__ float Ws[3][BN][PAD];

    const int tid  = threadIdx.x;
    const int lane = tid & 31, wid = tid >> 5;
    const int wm = (wid & 3) * 32, wn = (wid >> 2) * 32;
    const int g = lane >> 2, t = lane & 3;
    const int bm = blockIdx.x * BM;
    const int bn = (EPI == 3) ? 0 : blockIdx.y * BN;

    const float* Wp = W;
    const float* bp = bias;
    float* Cp = C;
    if (EPI == 3 && blockIdx.y == 1) { Wp = aux0; bp = aux1; Cp = aux2; }

    const int ar0 = tid >> 2;            // 0..63
    const int ak  = (tid & 3) * 4;
    const int nTiles = K / BK;

    const bool wok = (bn + ar0) < Nfull;
    const int wrow = wok ? (bn + ar0) : 0;

    uint32_t sA0 = (uint32_t)__cvta_generic_to_shared(&As[0][ar0][ak]);
    uint32_t sA1 = (uint32_t)__cvta_generic_to_shared(&As[0][ar0 + 64][ak]);
    uint32_t sW0 = (uint32_t)__cvta_generic_to_shared(&Ws[0][ar0][ak]);
    const uint32_t bufA = BM * PAD * 4;  // bytes per As buffer
    const uint32_t bufW = BN * PAD * 4;

    auto issue = [&](int kt, int b) {
        int k0 = kt * BK + ak;
        cp16(sA0 + b * bufA, A + (size_t)(bm + ar0) * lda + k0, true);
        cp16(sA1 + b * bufA, A + (size_t)(bm + ar0 + 64) * lda + k0, true);
        cp16(sW0 + b * bufW, Wp + (size_t)wrow * ldw + k0, wok);
    };

    float acc[2][4][4];
#pragma unroll
    for (int i = 0; i < 2; i++)
#pragma unroll
        for (int j = 0; j < 4; j++)
#pragma unroll
            for (int l = 0; l < 4; l++) acc[i][j][l] = 0.f;

    issue(0, 0); CP_COMMIT();
    issue(1, 1); CP_COMMIT();

    int cur = 0;
    for (int kt = 0; kt < nTiles; kt++) {
        CP_WAIT1();
        __syncthreads();
        if (kt + 2 < nTiles) issue(kt + 2, (kt + 2) % 3);
        CP_COMMIT();

#pragma unroll
        for (int ks = 0; ks < 2; ks++) {
            const int kb = ks * 8;
            uint32_t a[2][4];
#pragma unroll
            for (int mt = 0; mt < 2; mt++) {
                int row = wm + mt * 16 + g;
                a[mt][0] = __float_as_uint(As[cur][row][kb + t]);
                a[mt][1] = __float_as_uint(As[cur][row + 8][kb + t]);
                a[mt][2] = __float_as_uint(As[cur][row][kb + t + 4]);
                a[mt][3] = __float_as_uint(As[cur][row + 8][kb + t + 4]);
            }
#pragma unroll
            for (int nt = 0; nt < 4; nt++) {
                int nc = wn + nt * 8 + g;
                uint32_t b0 = __float_as_uint(Ws[cur][nc][kb + t]);
                uint32_t b1 = __float_as_uint(Ws[cur][nc][kb + t + 4]);
                mma_tf32(acc[0][nt], a[0], b0, b1);
                mma_tf32(acc[1][nt], a[1], b0, b1);
            }
        }
        cur = (cur + 1) % 3;
    }

#pragma unroll
    for (int mt = 0; mt < 2; mt++) {
#pragma unroll
        for (int nt = 0; nt < 4; nt++) {
#pragma unroll
            for (int ci = 0; ci < 4; ci++) {
                int row = bm + wm + mt * 16 + g + ((ci >= 2) ? 8 : 0);
                int col = bn + wn + nt * 8 + t * 2 + (ci & 1);
                float v = acc[mt][nt][ci];
                if (EPI == 0) {
                    if (col < Nfull) C[(size_t)row * ldc + col] = v;
                } else if (EPI == 1) {
                    C[(size_t)row * ldc + col] = cvt_tf32(v + bias[col]);
                } else if (EPI == 2) {
                    if (col < DI) {
                        float u = v * aux0[col * 4 + 3] + aux1[col];
                        C[(size_t)row * DI + col] = cvt_tf32(u * fast_sigmoid(u)); // U2
                    } else {
                        aux2[(size_t)row * DI + (col - DI)] = v * fast_sigmoid(v); // G
                    }
                } else if (EPI == 3) {
                    float h = v + bp[col];
                    if (blockIdx.y == 0) h = fast_tanh(h);
                    else                 h = fminf(fmaxf(h, -5.f), 2.f);
                    Cp[(size_t)row * ADIM + col] = h;
                } else { // EPI == 4: plain, tf32-rounded
                    C[(size_t)row * ldc + col] = cvt_tf32(v);
                }
            }
        }
    }
}

// Fused: delta = softplus(XD[:,:16]@dtw^T + b); bc = B.C;
//        Y = cvt_tf32(U2 * (delta*bc + Dskip) * silu(z))
#define RB2 8
__global__ void __launch_bounds__(512)
delta_ygate(const float* __restrict__ XD, const float* __restrict__ dtw,
            const float* __restrict__ dtb, const float* __restrict__ U2,
            const float* __restrict__ G, const float* __restrict__ Dskip,
            float* __restrict__ Y) {
    __shared__ float sXD[RB2][XDW];
    __shared__ float sbc[RB2];
    const int tid = threadIdx.x;
    const int r0 = blockIdx.x * RB2;

    if (tid < RB2 * 12) {
        int r = tid / 12, c4 = (tid % 12) * 4;
        *(float4*)&sXD[r][c4] = *(const float4*)&XD[(size_t)(r0 + r) * XDW + c4];
    }
    __syncthreads();
    if (tid < RB2) {
        float s = 0.f;
#pragma unroll
        for (int k = 0; k < DS; k++) s += sXD[tid][DTR + k] * sXD[tid][DTR + DS + k];
        sbc[tid] = s;
    }

    float w[DTR];
#pragma unroll
    for (int i = 0; i < 4; i++)
        *(float4*)&w[i * 4] = *(const float4*)(dtw + (size_t)tid * DTR + i * 4);
    const float bv = dtb[tid];
    const float dv = Dskip[tid];
    __syncthreads();

    size_t base = (size_t)r0 * DI;
    float u = U2[base + tid];
    float gg = G[base + tid];
#pragma unroll
    for (int r = 0; r < RB2; r++) {
        float un, gn;
        if (r + 1 < RB2) {
            un = U2[base + DI + tid];
            gn = G[base + DI + tid];
        }
        float acc = bv;
#pragma unroll
        for (int k = 0; k < DTR; k++) acc += w[k] * sXD[r][k];
        float de = fast_softplus(acc);
        Y[base + tid] = cvt_tf32(u * (de * sbc[r] + dv) * gg);
        base += DI;
        u = un; gg = gn;
    }
}

extern "C" void kernel_launch(void* const* d_in, const int* in_sizes, int n_in,
                              void* d_out, int out_size) {
    const float* perception = (const float*)d_in[0];
    const float* W_in       = (const float*)d_in[1];
    const float* b_in       = (const float*)d_in[2];
    const float* mu_w       = (const float*)d_in[3];
    const float* mu_b       = (const float*)d_in[4];
    const float* ls_w       = (const float*)d_in[5];
    const float* ls_b       = (const float*)d_in[6];
    const float* in_proj_w  = (const float*)d_in[7];
    const float* conv_w     = (const float*)d_in[8];
    const float* conv_b     = (const float*)d_in[9];
    const float* x_proj_w   = (const float*)d_in[10];
    const float* dt_proj_w  = (const float*)d_in[11];
    const float* dt_proj_b  = (const float*)d_in[12];
    const float* Dskip      = (const float*)d_in[14];
    const float* out_proj_w = (const float*)d_in[15];

    float* out = (float*)d_out;

    float *P, *Wts, *X, *U2, *G, *XD, *Y, *H;
    cudaGetSymbolAddress((void**)&P,  g_P);
    cudaGetSymbolAddress((void**)&Wts, g_W);
    cudaGetSymbolAddress((void**)&X,  g_X);
    cudaGetSymbolAddress((void**)&U2, g_U2);
    cudaGetSymbolAddress((void**)&G,  g_G);
    cudaGetSymbolAddress((void**)&XD, g_XD);
    cudaGetSymbolAddress((void**)&Y,  g_Y);
    cudaGetSymbolAddress((void**)&H,  g_H);

    const int MB = BATCH / 128;   // 64

    // 0) pre-round perception + weights to tf32
    preround<<<(NP_TOTAL + NW_TOTAL + 255) / 256, 256>>>(
        perception, W_in, in_proj_w, x_proj_w, out_proj_w, mu_w, ls_w, P, Wts);

    // 1) X = cvt(perc @ W_in^T + b_in)       [8192,256] K=512
    gemm_cp<1><<<dim3(MB, DM / 64), 256>>>(P, PDIM, Wts + OFF_WIN, PDIM, b_in,
                                           X, DM, DM, PDIM,
                                           nullptr, nullptr, nullptr);
    // 2) in_proj + silu-conv + silu(z)       [8192,1024] K=256 -> U2, G
    gemm_cp<2><<<dim3(MB, (2 * DI) / 64), 256>>>(X, DM, Wts + OFF_INPJ, DM,
                                                 nullptr, U2, DI, 2 * DI, DM,
                                                 conv_w, conv_b, G);
    // 3) XD = U2 @ x_proj^T                  [8192,48] K=512
    gemm_cp<0><<<dim3(MB, 1), 256>>>(U2, DI, Wts + OFF_XPJ, DI, nullptr,
                                     XD, XDW, XDW, DI,
                                     nullptr, nullptr, nullptr);
    // 4) delta + bc + gate -> Y              [8192,512]
    delta_ygate<<<BATCH / RB2, 512>>>(XD, dt_proj_w, dt_proj_b, U2, G, Dskip, Y);
    // 5) H = cvt(Y @ out_proj^T)             [8192,256] K=512
    gemm_cp<4><<<dim3(MB, DM / 64), 256>>>(Y, DI, Wts + OFF_OPJ, DI, nullptr,
                                           H, DM, DM, DI,
                                           nullptr, nullptr, nullptr);
    // 6) heads: mu (by=0) | log_std (by=1)   [8192,64] K=256
    gemm_cp<3><<<dim3(MB, 2), 256>>>(H, DM, Wts + OFF_MUW, DM, mu_b,
                                     out, ADIM, ADIM, DM,
                                     Wts + OFF_LSW, ls_b,
                                     out + (size_t)BATCH * ADIM);
    (void)in_sizes; (void)n_in; (void)out_size;
}

// round 11
// speedup vs baseline: 1.1278x; 1.0423x over previous
#include <cuda_runtime.h>
#include <math.h>
#include <stdint.h>

#define BATCH 8192
#define PDIM  512
#define DM    256
#define DI    512
#define DTR   16
#define DS    16
#define ADIM  64
#define XDW   48

// ---- static scratch ----
__device__ float g_P[BATCH * PDIM];      // tf32-rounded perception
__device__ float g_W[417792];            // tf32 weights: W_in | in_proj | x_proj
__device__ float g_WC[128 * DI];         // combined head weights [mu;ls] @ out_proj
__device__ float g_X[BATCH * DM];
__device__ float g_U2[BATCH * DI];
__device__ float g_G[BATCH * DI];
__device__ float g_XD[4 * BATCH * XDW];  // split-K partials
__device__ float g_Y[BATCH * DI];

// weight offsets inside g_W (floats)
#define OFF_WIN   0          // 256x512
#define OFF_INPJ  131072     // 1024x256
#define OFF_XPJ   393216     // 48x512
#define NW_TOTAL  417792
#define NP_TOTAL  (BATCH * PDIM)

__device__ __forceinline__ float cvt_tf32(float x) {
    uint32_t u;
    asm("cvt.rna.tf32.f32 %0, %1;" : "=r"(u) : "f"(x));
    return __uint_as_float(u);
}

__device__ __forceinline__ void mma_tf32(float* c, const uint32_t* a,
                                         uint32_t b0, uint32_t b1) {
    asm volatile(
        "mma.sync.aligned.m16n8k8.row.col.f32.tf32.tf32.f32 "
        "{%0,%1,%2,%3},{%4,%5,%6,%7},{%8,%9},{%0,%1,%2,%3};"
        : "+f"(c[0]), "+f"(c[1]), "+f"(c[2]), "+f"(c[3])
        : "r"(a[0]), "r"(a[1]), "r"(a[2]), "r"(a[3]), "r"(b0), "r"(b1));
}

// ---- cp.async ----
__device__ __forceinline__ void cp16(uint32_t dst, const float* src, bool ok) {
    int sz = ok ? 16 : 0;
    asm volatile("cp.async.ca.shared.global [%0], [%1], 16, %2;"
                 :: "r"(dst), "l"(src), "r"(sz) : "memory");
}
#define CP_COMMIT() asm volatile("cp.async.commit_group;" ::: "memory")
#define CP_WAIT1()  asm volatile("cp.async.wait_group 1;" ::: "memory")

// ---- fast transcendentals ----
__device__ __forceinline__ float fast_sigmoid(float x) {
    return __fdividef(1.f, 1.f + __expf(-x));
}
__device__ __forceinline__ float fast_softplus(float x) {
    return (x > 15.f) ? x : __logf(1.f + __expf(x));
}
__device__ __forceinline__ float fast_tanh(float x) {
    float e = __expf(-2.f * fabsf(x));
    float t = __fdividef(1.f - e, 1.f + e);
    return copysignf(t, x);
}

// Pre-round perception + GEMM weights to tf32.
__global__ void __launch_bounds__(256)
preround(const float* __restrict__ P,
         const float* __restrict__ w_in,  const float* __restrict__ in_proj,
         const float* __restrict__ x_proj,
         float* __restrict__ gP, float* __restrict__ gW) {
    int idx = blockIdx.x * 256 + threadIdx.x;
    if (idx < NP_TOTAL) {
        gP[idx] = cvt_tf32(P[idx]);
        return;
    }
    int j = idx - NP_TOTAL;
    if (j >= NW_TOTAL) return;
    float v;
    if      (j < OFF_INPJ) v = w_in[j - OFF_WIN];
    else if (j < OFF_XPJ)  v = in_proj[j - OFF_INPJ];
    else                   v = x_proj[j - OFF_XPJ];
    gW[j] = cvt_tf32(v);
}

// WC[j,d] = sum_m Mstack[j,m] * out_proj[m,d]   (j<128, m<256, d<512), fp32.
// grid (2, 8), 64x64 tiles, 256 threads.
__global__ void __launch_bounds__(256)
combine_heads(const float* __restrict__ mu_w, const float* __restrict__ ls_w,
              const float* __restrict__ out_proj, float* __restrict__ WC) {
    __shared__ float sM[64][65];
    __shared__ float sO[64][65];
    const int tid = threadIdx.x;
    const int bj = blockIdx.x * 64, bd = blockIdx.y * 64;
    const int ty = tid >> 4, tx = tid & 15;

    float acc[4][4];
#pragma unroll
    for (int i = 0; i < 4; i++)
#pragma unroll
        for (int j = 0; j < 4; j++) acc[i][j] = 0.f;

    for (int k0 = 0; k0 < DM; k0 += 64) {
        for (int i = tid; i < 64 * 16; i += 256) {
            int r = i >> 4, q = (i & 15) * 4;
            int jr = bj + r;
            const float* src = (jr < ADIM)
                ? (mu_w + (size_t)jr * DM + k0 + q)
                : (ls_w + (size_t)(jr - ADIM) * DM + k0 + q);
            float4 v = *(const float4*)src;
            sM[r][q] = v.x; sM[r][q + 1] = v.y; sM[r][q + 2] = v.z; sM[r][q + 3] = v.w;
        }
        for (int i = tid; i < 64 * 16; i += 256) {
            int r = i >> 4, q = (i & 15) * 4;
            float4 v = *(const float4*)(out_proj + (size_t)(k0 + r) * DI + bd + q);
            sO[r][q] = v.x; sO[r][q + 1] = v.y; sO[r][q + 2] = v.z; sO[r][q + 3] = v.w;
        }
        __syncthreads();
#pragma unroll 8
        for (int k = 0; k < 64; k++) {
            float a[4], b[4];
#pragma unroll
            for (int i = 0; i < 4; i++) { a[i] = sM[ty * 4 + i][k]; b[i] = sO[k][tx * 4 + i]; }
#pragma unroll
            for (int i = 0; i < 4; i++)
#pragma unroll
                for (int j = 0; j < 4; j++) acc[i][j] += a[i] * b[j];
        }
        __syncthreads();
    }
#pragma unroll
    for (int i = 0; i < 4; i++)
#pragma unroll
        for (int j = 0; j < 4; j++)
            WC[(size_t)(bj + ty * 4 + i) * DI + bd + tx * 4 + j] = cvt_tf32(acc[i][j]);
}

// C[M,N] = A[M,K] @ W[N,K]^T. Inputs pre-rounded tf32. BM=128 BN=64 BK=16,
// 256 thr, warp tile 32x32, cp.async 3-stage pipeline, smem [row][20].
// blockIdx.z = split-K slice (EPI0 only): A/W advance z*K, C -> partial z.
// EPI: 0 plain split-K (guard col<Nfull), 1 X=cvt(v+bias), 2 in_proj fused,
//      3 combined heads (cols 0-63 mu tanh, 64-127 log_std clip)
template <int EPI>
__global__ void __launch_bounds__(256)
gemm_cp(const float* __restrict__ A, int lda,
        const float* __restrict__ W, int ldw, const float* __restrict__ bias,
        float* __restrict__ C, int ldc, int Nfull, int K,
        const float* __restrict__ aux0, const float* __restrict__ aux1,
        float* __restrict__ aux2) {
    const int BM = 128, BN = 64, BK = 16, PAD = 20;
    __shared__ float As[3][BM][PAD];
    __shared__ float Ws[3][BN][PAD];

    const int tid  = threadIdx.x;
    const int lane = tid & 31, wid = tid >> 5;
    const int wm = (wid & 3) * 32, wn = (wid >> 2) * 32;
    const int g = lane >> 2, t = lane & 3;
    const int bm = blockIdx.x * BM;
    const int bn = blockIdx.y * BN;

    const int kz = blockIdx.z * K;
    const float* Ap = A + kz;
    const float* Wp = W + kz;
    float* Cz = (EPI == 0) ? (C + (size_t)blockIdx.z * BATCH * XDW) : C;

    const int ar0 = tid >> 2;            // 0..63
    const int ak  = (tid & 3) * 4;
    const int nTiles = K / BK;

    const bool wok = (bn + ar0) < Nfull;
    const int wrow = wok ? (bn + ar0) : 0;

    uint32_t sA0 = (uint32_t)__cvta_generic_to_shared(&As[0][ar0][ak]);
    uint32_t sA1 = (uint32_t)__cvta_generic_to_shared(&As[0][ar0 + 64][ak]);
    uint32_t sW0 = (uint32_t)__cvta_generic_to_shared(&Ws[0][ar0][ak]);
    const uint32_t bufA = BM * PAD * 4;
    const uint32_t bufW = BN * PAD * 4;

    auto issue = [&](int kt, int b) {
        int k0 = kt * BK + ak;
        cp16(sA0 + b * bufA, Ap + (size_t)(bm + ar0) * lda + k0, true);
        cp16(sA1 + b * bufA, Ap + (size_t)(bm + ar0 + 64) * lda + k0, true);
        cp16(sW0 + b * bufW, Wp + (size_t)wrow * ldw + k0, wok);
    };

    float acc[2][4][4];
#pragma unroll
    for (int i = 0; i < 2; i++)
#pragma unroll
        for (int j = 0; j < 4; j++)
#pragma unroll
            for (int l = 0; l < 4; l++) acc[i][j][l] = 0.f;

    issue(0, 0); CP_COMMIT();
    issue(1, 1); CP_COMMIT();

    int cur = 0;
    for (int kt = 0; kt < nTiles; kt++) {
        CP_WAIT1();
        __syncthreads();
        if (kt + 2 < nTiles) issue(kt + 2, (kt + 2) % 3);
        CP_COMMIT();

#pragma unroll
        for (int ks = 0; ks < 2; ks++) {
            const int kb = ks * 8;
            uint32_t a[2][4];
#pragma unroll
            for (int mt = 0; mt < 2; mt++) {
                int row = wm + mt * 16 + g;
                a[mt][0] = __float_as_uint(As[cur][row][kb + t]);
                a[mt][1] = __float_as_uint(As[cur][row + 8][kb + t]);
                a[mt][2] = __float_as_uint(As[cur][row][kb + t + 4]);
                a[mt][3] = __float_as_uint(As[cur][row + 8][kb + t + 4]);
            }
#pragma unroll
            for (int nt = 0; nt < 4; nt++) {
                int nc = wn + nt * 8 + g;
                uint32_t b0 = __float_as_uint(Ws[cur][nc][kb + t]);
                uint32_t b1 = __float_as_uint(Ws[cur][nc][kb + t + 4]);
                mma_tf32(acc[0][nt], a[0], b0, b1);
                mma_tf32(acc[1][nt], a[1], b0, b1);
            }
        }
        cur = (cur + 1) % 3;
    }

#pragma unroll
    for (int mt = 0; mt < 2; mt++) {
#pragma unroll
        for (int nt = 0; nt < 4; nt++) {
#pragma unroll
            for (int ci = 0; ci < 4; ci++) {
                int row = bm + wm + mt * 16 + g + ((ci >= 2) ? 8 : 0);
                int col = bn + wn + nt * 8 + t * 2 + (ci & 1);
                float v = acc[mt][nt][ci];
                if (EPI == 0) {
                    if (col < Nfull) Cz[(size_t)row * ldc + col] = v;
                } else if (EPI == 1) {
                    C[(size_t)row * ldc + col] = cvt_tf32(v + bias[col]);
                } else if (EPI == 2) {
                    if (col < DI) {
                        float u = v * aux0[col * 4 + 3] + aux1[col];
                        C[(size_t)row * DI + col] = cvt_tf32(u * fast_sigmoid(u)); // U2
                    } else {
                        aux2[(size_t)row * DI + (col - DI)] = v * fast_sigmoid(v); // G
                    }
                } else { // EPI == 3: combined heads
                    if (col < ADIM) {
                        C[(size_t)row * ADIM + col] = fast_tanh(v + bias[col]);
                    } else {
                        float h = v + aux1[col - ADIM];
                        h = fminf(fmaxf(h, -5.f), 2.f);
                        aux2[(size_t)row * ADIM + (col - ADIM)] = h;
                    }
                }
            }
        }
    }
}

// Fused: XD = sum of 4 split-K partials; delta = softplus(XD[:,:16]@dtw^T+b);
//        bc = B.C;  Y = cvt_tf32(U2 * (delta*bc + Dskip) * silu(z))
#define RB2 8
__global__ void __launch_bounds__(512)
delta_ygate(const float* __restrict__ XD, const float* __restrict__ dtw,
            const float* __restrict__ dtb, const float* __restrict__ U2,
            const float* __restrict__ G, const float* __restrict__ Dskip,
            float* __restrict__ Y) {
    __shared__ float sXD[RB2][XDW];
    __shared__ float sbc[RB2];
    const int tid = threadIdx.x;
    const int r0 = blockIdx.x * RB2;

    if (tid < RB2 * 12) {
        int r = tid / 12, c4 = (tid % 12) * 4;
        size_t off = (size_t)(r0 + r) * XDW + c4;
        float4 s = *(const float4*)&XD[off];
#pragma unroll
        for (int p = 1; p < 4; p++) {
            float4 xp = *(const float4*)&XD[(size_t)p * BATCH * XDW + off];
            s.x += xp.x; s.y += xp.y; s.z += xp.z; s.w += xp.w;
        }
        *(float4*)&sXD[r][c4] = s;
    }
    __syncthreads();
    if (tid < RB2) {
        float s = 0.f;
#pragma unroll
        for (int k = 0; k < DS; k++) s += sXD[tid][DTR + k] * sXD[tid][DTR + DS + k];
        sbc[tid] = s;
    }

    float w[DTR];
#pragma unroll
    for (int i = 0; i < 4; i++)
        *(float4*)&w[i * 4] = *(const float4*)(dtw + (size_t)tid * DTR + i * 4);
    const float bv = dtb[tid];
    const float dv = Dskip[tid];
    __syncthreads();

    size_t base = (size_t)r0 * DI;
    float u = U2[base + tid];
    float gg = G[base + tid];
#pragma unroll
    for (int r = 0; r < RB2; r++) {
        float un, gn;
        if (r + 1 < RB2) {
            un = U2[base + DI + tid];
            gn = G[base + DI + tid];
        }
        float acc = bv;
#pragma unroll
        for (int k = 0; k < DTR; k++) acc += w[k] * sXD[r][k];
        float de = fast_softplus(acc);
        Y[base + tid] = cvt_tf32(u * (de * sbc[r] + dv) * gg);
        base += DI;
        u = un; gg = gn;
    }
}

extern "C" void kernel_launch(void* const* d_in, const int* in_sizes, int n_in,
                              void* d_out, int out_size) {
    const float* perception = (const float*)d_in[0];
    const float* W_in       = (const float*)d_in[1];
    const float* b_in       = (const float*)d_in[2];
    const float* mu_w       = (const float*)d_in[3];
    const float* mu_b       = (const float*)d_in[4];
    const float* ls_w       = (const float*)d_in[5];
    const float* ls_b       = (const float*)d_in[6];
    const float* in_proj_w  = (const float*)d_in[7];
    const float* conv_w     = (const float*)d_in[8];
    const float* conv_b     = (const float*)d_in[9];
    const float* x_proj_w   = (const float*)d_in[10];
    const float* dt_proj_w  = (const float*)d_in[11];
    const float* dt_proj_b  = (const float*)d_in[12];
    const float* Dskip      = (const float*)d_in[14];
    const float* out_proj_w = (const float*)d_in[15];

    float* out = (float*)d_out;

    float *P, *Wts, *WC, *X, *U2, *G, *XD, *Y;
    cudaGetSymbolAddress((void**)&P,   g_P);
    cudaGetSymbolAddress((void**)&Wts, g_W);
    cudaGetSymbolAddress((void**)&WC,  g_WC);
    cudaGetSymbolAddress((void**)&X,   g_X);
    cudaGetSymbolAddress((void**)&U2,  g_U2);
    cudaGetSymbolAddress((void**)&G,   g_G);
    cudaGetSymbolAddress((void**)&XD,  g_XD);
    cudaGetSymbolAddress((void**)&Y,   g_Y);

    const int MB = BATCH / 128;   // 64

    // 0) pre-round inputs + fold head weights through out_proj
    preround<<<(NP_TOTAL + NW_TOTAL + 255) / 256, 256>>>(
        perception, W_in, in_proj_w, x_proj_w, P, Wts);
    combine_heads<<<dim3(2, 8), 256>>>(mu_w, ls_w, out_proj_w, WC);

    // 1) X = cvt(perc @ W_in^T + b_in)       [8192,256] K=512
    gemm_cp<1><<<dim3(MB, DM / 64), 256>>>(P, PDIM, Wts + OFF_WIN, PDIM, b_in,
                                           X, DM, DM, PDIM,
                                           nullptr, nullptr, nullptr);
    // 2) in_proj + silu-conv + silu(z)       [8192,1024] K=256 -> U2, G
    gemm_cp<2><<<dim3(MB, (2 * DI) / 64), 256>>>(X, DM, Wts + OFF_INPJ, DM,
                                                 nullptr, U2, DI, 2 * DI, DM,
                                                 conv_w, conv_b, G);
    // 3) XD partials = U2 @ x_proj^T (split-K x4) [8192,48] K=4x128
    gemm_cp<0><<<dim3(MB, 1, 4), 256>>>(U2, DI, Wts + OFF_XPJ, DI, nullptr,
                                        XD, XDW, XDW, 128,
                                        nullptr, nullptr, nullptr);
    // 4) delta + bc + gate -> Y              [8192,512]
    delta_ygate<<<BATCH / RB2, 512>>>(XD, dt_proj_w, dt_proj_b, U2, G, Dskip, Y);
    // 5) heads = f(Y @ WC^T): mu|log_std     [8192,128] K=512
    gemm_cp<3><<<dim3(MB, 2), 256>>>(Y, DI, WC, DI, mu_b,
                                     out, ADIM, 128, DI,
                                     nullptr, ls_b, out + (size_t)BATCH * ADIM);
    (void)in_sizes; (void)n_in; (void)out_size;
}

// round 12
// speedup vs baseline: 1.1299x; 1.0019x over previous
#include <cuda_runtime.h>
#include <math.h>
#include <stdint.h>

#define BATCH 8192
#define PDIM  512
#define DM    256
#define DI    512
#define DTR   16
#define DS    16
#define ADIM  64
#define XDW   48

// ---- static scratch ----
__device__ float g_P[BATCH * PDIM];      // tf32-rounded perception
__device__ float g_W[417792];            // tf32 weights: W_in | in_proj | x_proj
__device__ float g_WC[128 * DI];         // combined head weights
__device__ float g_X[BATCH * DM];
__device__ float g_U2[BATCH * DI];
__device__ float g_G[BATCH * DI];
__device__ float g_XD[4 * BATCH * XDW];  // x_proj split-K partials
__device__ float g_Y[BATCH * DI];
__device__ float g_HP[2 * BATCH * 128];  // heads split-K partials

#define OFF_WIN   0
#define OFF_INPJ  131072
#define OFF_XPJ   393216
#define NW_TOTAL  417792
#define NP_TOTAL  (BATCH * PDIM)

__device__ __forceinline__ float cvt_tf32(float x) {
    uint32_t u;
    asm("cvt.rna.tf32.f32 %0, %1;" : "=r"(u) : "f"(x));
    return __uint_as_float(u);
}

__device__ __forceinline__ void mma_tf32(float* c, const uint32_t* a,
                                         uint32_t b0, uint32_t b1) {
    asm volatile(
        "mma.sync.aligned.m16n8k8.row.col.f32.tf32.tf32.f32 "
        "{%0,%1,%2,%3},{%4,%5,%6,%7},{%8,%9},{%0,%1,%2,%3};"
        : "+f"(c[0]), "+f"(c[1]), "+f"(c[2]), "+f"(c[3])
        : "r"(a[0]), "r"(a[1]), "r"(a[2]), "r"(a[3]), "r"(b0), "r"(b1));
}

__device__ __forceinline__ void cp16(uint32_t dst, const float* src, bool ok) {
    int sz = ok ? 16 : 0;
    asm volatile("cp.async.ca.shared.global [%0], [%1], 16, %2;"
                 :: "r"(dst), "l"(src), "r"(sz) : "memory");
}
#define CP_COMMIT() asm volatile("cp.async.commit_group;" ::: "memory")
#define CP_WAIT1()  asm volatile("cp.async.wait_group 1;" ::: "memory")

__device__ __forceinline__ float fast_sigmoid(float x) {
    return __fdividef(1.f, 1.f + __expf(-x));
}
__device__ __forceinline__ float fast_softplus(float x) {
    return (x > 15.f) ? x : __logf(1.f + __expf(x));
}
__device__ __forceinline__ float fast_tanh(float x) {
    float e = __expf(-2.f * fabsf(x));
    float t = __fdividef(1.f - e, 1.f + e);
    return copysignf(t, x);
}

__global__ void __launch_bounds__(256)
preround(const float* __restrict__ P,
         const float* __restrict__ w_in,  const float* __restrict__ in_proj,
         const float* __restrict__ x_proj,
         float* __restrict__ gP, float* __restrict__ gW) {
    int idx = blockIdx.x * 256 + threadIdx.x;
    if (idx < NP_TOTAL) {
        gP[idx] = cvt_tf32(P[idx]);
        return;
    }
    int j = idx - NP_TOTAL;
    if (j >= NW_TOTAL) return;
    float v;
    if      (j < OFF_INPJ) v = w_in[j - OFF_WIN];
    else if (j < OFF_XPJ)  v = in_proj[j - OFF_INPJ];
    else                   v = x_proj[j - OFF_XPJ];
    gW[j] = cvt_tf32(v);
}

// WC[j,d] = sum_m [mu_w;ls_w][j,m] * out_proj[m,d]
__global__ void __launch_bounds__(256)
combine_heads(const float* __restrict__ mu_w, const float* __restrict__ ls_w,
              const float* __restrict__ out_proj, float* __restrict__ WC) {
    __shared__ float sM[64][65];
    __shared__ float sO[64][65];
    const int tid = threadIdx.x;
    const int bj = blockIdx.x * 64, bd = blockIdx.y * 64;
    const int ty = tid >> 4, tx = tid & 15;

    float acc[4][4];
#pragma unroll
    for (int i = 0; i < 4; i++)
#pragma unroll
        for (int j = 0; j < 4; j++) acc[i][j] = 0.f;

    for (int k0 = 0; k0 < DM; k0 += 64) {
        for (int i = tid; i < 64 * 16; i += 256) {
            int r = i >> 4, q = (i & 15) * 4;
            int jr = bj + r;
            const float* src = (jr < ADIM)
                ? (mu_w + (size_t)jr * DM + k0 + q)
                : (ls_w + (size_t)(jr - ADIM) * DM + k0 + q);
            float4 v = *(const float4*)src;
            sM[r][q] = v.x; sM[r][q + 1] = v.y; sM[r][q + 2] = v.z; sM[r][q + 3] = v.w;
        }
        for (int i = tid; i < 64 * 16; i += 256) {
            int r = i >> 4, q = (i & 15) * 4;
            float4 v = *(const float4*)(out_proj + (size_t)(k0 + r) * DI + bd + q);
            sO[r][q] = v.x; sO[r][q + 1] = v.y; sO[r][q + 2] = v.z; sO[r][q + 3] = v.w;
        }
        __syncthreads();
#pragma unroll 8
        for (int k = 0; k < 64; k++) {
            float a[4], b[4];
#pragma unroll
            for (int i = 0; i < 4; i++) { a[i] = sM[ty * 4 + i][k]; b[i] = sO[k][tx * 4 + i]; }
#pragma unroll
            for (int i = 0; i < 4; i++)
#pragma unroll
                for (int j = 0; j < 4; j++) acc[i][j] += a[i] * b[j];
        }
        __syncthreads();
    }
#pragma unroll
    for (int i = 0; i < 4; i++)
#pragma unroll
        for (int j = 0; j < 4; j++)
            WC[(size_t)(bj + ty * 4 + i) * DI + bd + tx * 4 + j] = cvt_tf32(acc[i][j]);
}

// C[M,N] = A[M,K] @ W[N,K]^T. BM=128 BN=64 BK=16, 256 thr, warp tile 32x32,
// cp.async 3-stage. blockIdx.z = split-K slice (EPI0): partial at z*pstride.
// EPI: 0 plain split-K partials, 1 X=cvt(v+bias), 2 in_proj fused (U2|G)
template <int EPI>
__global__ void __launch_bounds__(256)
gemm_cp(const float* __restrict__ A, int lda,
        const float* __restrict__ W, int ldw, const float* __restrict__ bias,
        float* __restrict__ C, int ldc, int Nfull, int K, int pstride,
        const float* __restrict__ aux0, const float* __restrict__ aux1,
        float* __restrict__ aux2) {
    const int BM = 128, BN = 64, BK = 16, PAD = 20;
    __shared__ float As[3][BM][PAD];
    __shared__ float Ws[3][BN][PAD];

    const int tid  = threadIdx.x;
    const int lane = tid & 31, wid = tid >> 5;
    const int wm = (wid & 3) * 32, wn = (wid >> 2) * 32;
    const int g = lane >> 2, t = lane & 3;
    const int bm = blockIdx.x * BM;
    const int bn = blockIdx.y * BN;

    const int kz = blockIdx.z * K;
    const float* Ap = A + kz;
    const float* Wp = W + kz;
    float* Cz = (EPI == 0) ? (C + (size_t)blockIdx.z * pstride) : C;

    const int ar0 = tid >> 2;
    const int ak  = (tid & 3) * 4;
    const int nTiles = K / BK;

    const bool wok = (bn + ar0) < Nfull;
    const int wrow = wok ? (bn + ar0) : 0;

    uint32_t sA0 = (uint32_t)__cvta_generic_to_shared(&As[0][ar0][ak]);
    uint32_t sA1 = (uint32_t)__cvta_generic_to_shared(&As[0][ar0 + 64][ak]);
    uint32_t sW0 = (uint32_t)__cvta_generic_to_shared(&Ws[0][ar0][ak]);
    const uint32_t bufA = BM * PAD * 4;
    const uint32_t bufW = BN * PAD * 4;

    auto issue = [&](int kt, int b) {
        int k0 = kt * BK + ak;
        cp16(sA0 + b * bufA, Ap + (size_t)(bm + ar0) * lda + k0, true);
        cp16(sA1 + b * bufA, Ap + (size_t)(bm + ar0 + 64) * lda + k0, true);
        cp16(sW0 + b * bufW, Wp + (size_t)wrow * ldw + k0, wok);
    };

    float acc[2][4][4];
#pragma unroll
    for (int i = 0; i < 2; i++)
#pragma unroll
        for (int j = 0; j < 4; j++)
#pragma unroll
            for (int l = 0; l < 4; l++) acc[i][j][l] = 0.f;

    issue(0, 0); CP_COMMIT();
    issue(1, 1); CP_COMMIT();

    int cur = 0;
    for (int kt = 0; kt < nTiles; kt++) {
        CP_WAIT1();
        __syncthreads();
        if (kt + 2 < nTiles) issue(kt + 2, (kt + 2) % 3);
        CP_COMMIT();

#pragma unroll
        for (int ks = 0; ks < 2; ks++) {
            const int kb = ks * 8;
            uint32_t a[2][4];
#pragma unroll
            for (int mt = 0; mt < 2; mt++) {
                int row = wm + mt * 16 + g;
                a[mt][0] = __float_as_uint(As[cur][row][kb + t]);
                a[mt][1] = __float_as_uint(As[cur][row + 8][kb + t]);
                a[mt][2] = __float_as_uint(As[cur][row][kb + t + 4]);
                a[mt][3] = __float_as_uint(As[cur][row + 8][kb + t + 4]);
            }
#pragma unroll
            for (int nt = 0; nt < 4; nt++) {
                int nc = wn + nt * 8 + g;
                uint32_t b0 = __float_as_uint(Ws[cur][nc][kb + t]);
                uint32_t b1 = __float_as_uint(Ws[cur][nc][kb + t + 4]);
                mma_tf32(acc[0][nt], a[0], b0, b1);
                mma_tf32(acc[1][nt], a[1], b0, b1);
            }
        }
        cur = (cur + 1) % 3;
    }

#pragma unroll
    for (int mt = 0; mt < 2; mt++) {
#pragma unroll
        for (int nt = 0; nt < 4; nt++) {
#pragma unroll
            for (int ci = 0; ci < 4; ci++) {
                int row = bm + wm + mt * 16 + g + ((ci >= 2) ? 8 : 0);
                int col = bn + wn + nt * 8 + t * 2 + (ci & 1);
                float v = acc[mt][nt][ci];
                if (EPI == 0) {
                    if (col < Nfull) Cz[(size_t)row * ldc + col] = v;
                } else if (EPI == 1) {
                    C[(size_t)row * ldc + col] = cvt_tf32(v + bias[col]);
                } else if (EPI == 2) {
                    if (col < DI) {
                        float u = v * aux0[col * 4 + 3] + aux1[col];
                        C[(size_t)row * DI + col] = cvt_tf32(u * fast_sigmoid(u)); // U2
                    } else {
                        aux2[(size_t)row * DI + (col - DI)] = v * fast_sigmoid(v); // G
                    }
                }
            }
        }
    }
}

// heads epilogue: out = act(HP0 + HP1 + bias); cols 0-63 mu tanh -> out_mu,
// cols 64-127 log_std clip -> out_ls.  float4, one row-chunk per thread.
__global__ void __launch_bounds__(256)
heads_epi(const float* __restrict__ HP, const float* __restrict__ mu_b,
          const float* __restrict__ ls_b, float* __restrict__ out_mu,
          float* __restrict__ out_ls) {
    int idx = (blockIdx.x * 256 + threadIdx.x) * 4;   // over 8192*128
    int row = idx >> 7, col = idx & 127;
    float4 p0 = *(const float4*)&HP[idx];
    float4 p1 = *(const float4*)&HP[(size_t)BATCH * 128 + idx];
    if (col < ADIM) {
        const float4 b = *(const float4*)&mu_b[col];
        float4 o;
        o.x = fast_tanh(p0.x + p1.x + b.x);
        o.y = fast_tanh(p0.y + p1.y + b.y);
        o.z = fast_tanh(p0.z + p1.z + b.z);
        o.w = fast_tanh(p0.w + p1.w + b.w);
        *(float4*)&out_mu[(size_t)row * ADIM + col] = o;
    } else {
        const float4 b = *(const float4*)&ls_b[col - ADIM];
        float4 o;
        o.x = fminf(fmaxf(p0.x + p1.x + b.x, -5.f), 2.f);
        o.y = fminf(fmaxf(p0.y + p1.y + b.y, -5.f), 2.f);
        o.z = fminf(fmaxf(p0.z + p1.z + b.z, -5.f), 2.f);
        o.w = fminf(fmaxf(p0.w + p1.w + b.w, -5.f), 2.f);
        *(float4*)&out_ls[(size_t)row * ADIM + (col - ADIM)] = o;
    }
}

// Fused: XD = sum of 4 partials; delta = softplus(...); bc = B.C; gate.
#define RB2 8
__global__ void __launch_bounds__(512)
delta_ygate(const float* __restrict__ XD, const float* __restrict__ dtw,
            const float* __restrict__ dtb, const float* __restrict__ U2,
            const float* __restrict__ G, const float* __restrict__ Dskip,
            float* __restrict__ Y) {
    __shared__ float sXD[RB2][XDW];
    __shared__ float sbc[RB2];
    const int tid = threadIdx.x;
    const int r0 = blockIdx.x * RB2;

    if (tid < RB2 * 12) {
        int r = tid / 12, c4 = (tid % 12) * 4;
        size_t off = (size_t)(r0 + r) * XDW + c4;
        float4 s = *(const float4*)&XD[off];
#pragma unroll
        for (int p = 1; p < 4; p++) {
            float4 xp = *(const float4*)&XD[(size_t)p * BATCH * XDW + off];
            s.x += xp.x; s.y += xp.y; s.z += xp.z; s.w += xp.w;
        }
        *(float4*)&sXD[r][c4] = s;
    }
    __syncthreads();
    if (tid < RB2) {
        float s = 0.f;
#pragma unroll
        for (int k = 0; k < DS; k++) s += sXD[tid][DTR + k] * sXD[tid][DTR + DS + k];
        sbc[tid] = s;
    }

    float w[DTR];
#pragma unroll
    for (int i = 0; i < 4; i++)
        *(float4*)&w[i * 4] = *(const float4*)(dtw + (size_t)tid * DTR + i * 4);
    const float bv = dtb[tid];
    const float dv = Dskip[tid];
    __syncthreads();

    size_t base = (size_t)r0 * DI;
    float u = U2[base + tid];
    float gg = G[base + tid];
#pragma unroll
    for (int r = 0; r < RB2; r++) {
        float un, gn;
        if (r + 1 < RB2) {
            un = U2[base + DI + tid];
            gn = G[base + DI + tid];
        }
        float acc = bv;
#pragma unroll
        for (int k = 0; k < DTR; k++) acc += w[k] * sXD[r][k];
        float de = fast_softplus(acc);
        Y[base + tid] = cvt_tf32(u * (de * sbc[r] + dv) * gg);
        base += DI;
        u = un; gg = gn;
    }
}

extern "C" void kernel_launch(void* const* d_in, const int* in_sizes, int n_in,
                              void* d_out, int out_size) {
    const float* perception = (const float*)d_in[0];
    const float* W_in       = (const float*)d_in[1];
    const float* b_in       = (const float*)d_in[2];
    const float* mu_w       = (const float*)d_in[3];
    const float* mu_b       = (const float*)d_in[4];
    const float* ls_w       = (const float*)d_in[5];
    const float* ls_b       = (const float*)d_in[6];
    const float* in_proj_w  = (const float*)d_in[7];
    const float* conv_w     = (const float*)d_in[8];
    const float* conv_b     = (const float*)d_in[9];
    const float* x_proj_w   = (const float*)d_in[10];
    const float* dt_proj_w  = (const float*)d_in[11];
    const float* dt_proj_b  = (const float*)d_in[12];
    const float* Dskip      = (const float*)d_in[14];
    const float* out_proj_w = (const float*)d_in[15];

    float* out = (float*)d_out;

    float *P, *Wts, *WC, *X, *U2, *G, *XD, *Y, *HP;
    cudaGetSymbolAddress((void**)&P,   g_P);
    cudaGetSymbolAddress((void**)&Wts, g_W);
    cudaGetSymbolAddress((void**)&WC,  g_WC);
    cudaGetSymbolAddress((void**)&X,   g_X);
    cudaGetSymbolAddress((void**)&U2,  g_U2);
    cudaGetSymbolAddress((void**)&G,   g_G);
    cudaGetSymbolAddress((void**)&XD,  g_XD);
    cudaGetSymbolAddress((void**)&Y,   g_Y);
    cudaGetSymbolAddress((void**)&HP,  g_HP);

    const int MB = BATCH / 128;   // 64

    // 0) pre-round + fold heads through out_proj
    preround<<<(NP_TOTAL + NW_TOTAL + 255) / 256, 256>>>(
        perception, W_in, in_proj_w, x_proj_w, P, Wts);
    combine_heads<<<dim3(2, 8), 256>>>(mu_w, ls_w, out_proj_w, WC);

    // 1) X = cvt(perc @ W_in^T + b_in)       [8192,256] K=512
    gemm_cp<1><<<dim3(MB, DM / 64), 256>>>(P, PDIM, Wts + OFF_WIN, PDIM, b_in,
                                           X, DM, DM, PDIM, 0,
                                           nullptr, nullptr, nullptr);
    // 2) in_proj + silu-conv + silu(z)       [8192,1024] K=256 -> U2, G
    gemm_cp<2><<<dim3(MB, (2 * DI) / 64), 256>>>(X, DM, Wts + OFF_INPJ, DM,
                                                 nullptr, U2, DI, 2 * DI, DM, 0,
                                                 conv_w, conv_b, G);
    // 3) XD partials = U2 @ x_proj^T (split-K x4) [8192,48]
    gemm_cp<0><<<dim3(MB, 1, 4), 256>>>(U2, DI, Wts + OFF_XPJ, DI, nullptr,
                                        XD, XDW, XDW, 128, BATCH * XDW,
                                        nullptr, nullptr, nullptr);
    // 4) delta + bc + gate -> Y              [8192,512]
    delta_ygate<<<BATCH / RB2, 512>>>(XD, dt_proj_w, dt_proj_b, U2, G, Dskip, Y);
    // 5) head partials = Y @ WC^T (split-K x2) [8192,128]
    gemm_cp<0><<<dim3(MB, 2, 2), 256>>>(Y, DI, WC, DI, nullptr,
                                        HP, 128, 128, 256, BATCH * 128,
                                        nullptr, nullptr, nullptr);
    // 6) heads epilogue: reduce + bias + tanh/clip
    heads_epi<<<(BATCH * 128) / (256 * 4), 256>>>(HP, mu_b, ls_b,
                                                  out, out + (size_t)BATCH * ADIM);
    (void)in_sizes; (void)n_in; (void)out_size;
}